// round 15
// baseline (speedup 1.0000x reference)
#include <cuda_runtime.h>
#include <cuda_fp16.h>
#include <cstdint>

// Shapes (fixed)
#define N_NODES 8192
#define D_IN    200
#define D_OUT   128
#define NEG_SLOPE 0.01f

// GEMM tiling (R4-proven core), split-K overlapped with K1 via flags
#define BM      64
#define BKC     64                 // K per chunk = one 64-row flag group
#define SPLITS  4
#define CPS     32                 // chunks per split (8192/64/4)
#define STAGES  4
#define A_TILE_B (BM * BKC * 2)          // 8 KB
#define B_TILE_B (D_OUT * BKC * 2)       // 16 KB
#define STAGE_B  (A_TILE_B + B_TILE_B)   // 24 KB
#define NUNITS   512                     // 128 slabs x 4 splits
#define GRID_FUSED 8704                  // 17*512; bid%17==16 -> gemm unit
#define SWZ(off) ((off) ^ (((off) >> 3) & 0x70))

// Scratch (__device__ globals: allocation-free rule)
__device__ float  g_dis[N_NODES];                     // d^{-1/2} fp32 (reduce)
__device__ __half g_dish[N_NODES];                    // d^{-1/2} fp16 (gemm)
__device__ __half g_Ah[(size_t)N_NODES * N_NODES];    // fp16 sigmoid-clamp(A)
__device__ __half g_Bt[(size_t)D_OUT * N_NODES];      // [n][k] fp16 (HW+b), UNscaled
__device__ float  g_part[(size_t)SPLITS * N_NODES * D_OUT];  // split-K partials
__device__ int    g_done[N_NODES / 64];               // per-64-row-group flags

// ---------------------------------------------------------------------------
// Kernel A: g_Bt[j][k] = fp16(H[k,:]@W[:,j] + b[j])  — independent of K1!
// ---------------------------------------------------------------------------
#define K2_ROWS 16
__global__ void __launch_bounds__(256) k_hw(
    const float* __restrict__ H, const float* __restrict__ W,
    const float* __restrict__ b)
{
    __shared__ float hs[K2_ROWS][D_IN];
    const int kb = blockIdx.x * K2_ROWS;
    const int tid = threadIdx.x;

    for (int idx = tid; idx < K2_ROWS * (D_IN / 4); idx += 256) {
        const int r = idx / (D_IN / 4), c = idx % (D_IN / 4);
        reinterpret_cast<float4*>(&hs[r][0])[c] =
            reinterpret_cast<const float4*>(H + (size_t)(kb + r) * D_IN)[c];
    }
    __syncthreads();

    const int ty = tid >> 5;
    const int tx = tid & 31;
    const int j0 = tx * 4;
    const int k0 = kb + ty * 2;

    const float4 bj = *reinterpret_cast<const float4*>(b + j0);
    float4 acc0 = bj, acc1 = bj;
    const float* h0p = hs[ty * 2];
    const float* h1p = hs[ty * 2 + 1];

    #pragma unroll 4
    for (int i = 0; i < D_IN; i++) {
        const float4 w4 = *reinterpret_cast<const float4*>(W + i * D_OUT + j0);
        const float h0 = h0p[i];
        const float h1 = h1p[i];
        acc0.x = fmaf(h0, w4.x, acc0.x);
        acc0.y = fmaf(h0, w4.y, acc0.y);
        acc0.z = fmaf(h0, w4.z, acc0.z);
        acc0.w = fmaf(h0, w4.w, acc0.w);
        acc1.x = fmaf(h1, w4.x, acc1.x);
        acc1.y = fmaf(h1, w4.y, acc1.y);
        acc1.z = fmaf(h1, w4.z, acc1.z);
        acc1.w = fmaf(h1, w4.w, acc1.w);
    }

    __half2 p;
    p = __floats2half2_rn(acc0.x, acc1.x);
    *reinterpret_cast<__half2*>(&g_Bt[(size_t)(j0 + 0) * N_NODES + k0]) = p;
    p = __floats2half2_rn(acc0.y, acc1.y);
    *reinterpret_cast<__half2*>(&g_Bt[(size_t)(j0 + 1) * N_NODES + k0]) = p;
    p = __floats2half2_rn(acc0.z, acc1.z);
    *reinterpret_cast<__half2*>(&g_Bt[(size_t)(j0 + 2) * N_NODES + k0]) = p;
    p = __floats2half2_rn(acc0.w, acc1.w);
    *reinterpret_cast<__half2*>(&g_Bt[(size_t)(j0 + 3) * N_NODES + k0]) = p;
}

// ---------------------------------------------------------------------------
// helpers
// ---------------------------------------------------------------------------
__device__ __forceinline__ uint32_t s2u(const void* p) {
    uint32_t a;
    asm("{ .reg .u64 t; cvta.to.shared.u64 t, %1; cvt.u32.u64 %0, t; }"
        : "=r"(a) : "l"(p));
    return a;
}
__device__ __forceinline__ void cp16(uint32_t dst, const void* src) {
    asm volatile("cp.async.cg.shared.global [%0], [%1], 16;"
                 :: "r"(dst), "l"(src) : "memory");
}
__device__ __forceinline__ void ldsm4(uint32_t* r, uint32_t addr) {
    asm volatile("ldmatrix.sync.aligned.m8n8.x4.shared.b16 {%0,%1,%2,%3}, [%4];"
                 : "=r"(r[0]), "=r"(r[1]), "=r"(r[2]), "=r"(r[3]) : "r"(addr));
}
__device__ __forceinline__ void hmma(float* d, const uint32_t* a,
                                     uint32_t b0, uint32_t b1) {
    asm volatile(
        "mma.sync.aligned.m16n8k16.row.col.f32.f16.f16.f32 "
        "{%0,%1,%2,%3},{%4,%5,%6,%7},{%8,%9},{%0,%1,%2,%3};"
        : "+f"(d[0]), "+f"(d[1]), "+f"(d[2]), "+f"(d[3])
        : "r"(a[0]), "r"(a[1]), "r"(a[2]), "r"(a[3]), "r"(b0), "r"(b1));
}
__device__ __forceinline__ uint32_t hmul2u(uint32_t a, uint32_t b) {
    uint32_t r;
    asm("mul.rn.f16x2 %0, %1, %2;" : "=r"(r) : "r"(a), "r"(b));
    return r;
}

// ---------------------------------------------------------------------------
// Fused kernel: 8704 blocks.
//   bid%17 != 16 : K1 row-block (sigmoid+clamp -> fp32 A' + fp16 mirror,
//                  rowsum -> dis (fp32+fp16), then flag its 64-row group).
//   bid%17 == 16 : GEMM work-unit (slab g, K-split s): spins on flags, runs
//                  the R4-proven cp.async/ldsm/HMMA pipeline over K/4, scales
//                  B fragments by dis[k] (fp16), writes raw partial to g_part.
// ---------------------------------------------------------------------------
__global__ void __launch_bounds__(256) k_fused(
    const float* __restrict__ A, float* __restrict__ Aout)
{
    extern __shared__ __align__(1024) char dsm[];
    const int bid = blockIdx.x;
    const int t = threadIdx.x;

    if (bid % 17 != 16) {
        // ================= K1 role =================
        const int row = bid - (bid + 1) / 17;
        const float4* ap = reinterpret_cast<const float4*>(A + (size_t)row * N_NODES);
        float4* op = reinterpret_cast<float4*>(Aout + (size_t)row * N_NODES);
        uint2* hp = reinterpret_cast<uint2*>(g_Ah + (size_t)row * N_NODES);

        float sum = 0.0f;
        #pragma unroll 4
        for (int i = t; i < N_NODES / 4; i += 256) {
            float4 v = ap[i];
            float4 s;
            s.x = fmaxf(__fdividef(1.0f, 1.0f + __expf(-v.x)), 0.1f);
            s.y = fmaxf(__fdividef(1.0f, 1.0f + __expf(-v.y)), 0.1f);
            s.z = fmaxf(__fdividef(1.0f, 1.0f + __expf(-v.z)), 0.1f);
            s.w = fmaxf(__fdividef(1.0f, 1.0f + __expf(-v.w)), 0.1f);
            op[i] = s;
            __half2 p0 = __floats2half2_rn(s.x, s.y);
            __half2 p1 = __floats2half2_rn(s.z, s.w);
            uint2 u;
            u.x = *reinterpret_cast<uint32_t*>(&p0);
            u.y = *reinterpret_cast<uint32_t*>(&p1);
            hp[i] = u;
            sum += (s.x + s.y) + (s.z + s.w);
        }

        #pragma unroll
        for (int off = 16; off > 0; off >>= 1)
            sum += __shfl_xor_sync(0xFFFFFFFFu, sum, off);

        __shared__ float ws[8];
        const int wid = t >> 5, lane = t & 31;
        if (lane == 0) ws[wid] = sum;
        __syncthreads();
        if (t == 0) {
            float tot = 0.0f;
            #pragma unroll
            for (int w = 0; w < 8; w++) tot += ws[w];
            const float d = rsqrtf(tot);
            g_dis[row] = d;
            g_dish[row] = __float2half(d);
        }
        __threadfence();          // publish all this block's writes
        __syncthreads();
        if (t == 0) atomicAdd(&g_done[row >> 6], 1);
        return;
    }

    // ================= GEMM role =================
    const int u  = bid / 17;          // 0..511
    const int s  = u & 3;             // K split
    const int g  = u >> 2;            // slab 0..127
    const int m0 = g * BM;
    const int ck0 = s * CPS;

    const int wid = t >> 5, lane = t & 31;
    const int wm  = wid & 1;
    const int wn  = wid >> 1;
    const uint32_t smBase = s2u(dsm);

    // wait until this slab's A rows (group g) are published
    if (t == 0)
        while (*(volatile int*)&g_done[g] < 64) __nanosleep(256);
    __syncthreads();
    __threadfence();

    // staging maps (R4): 16B chunks, 128B rows, XOR swizzle; K offset by ck0
    const int sr  = t >> 3;
    const int sc  = (t & 7) * 16;
    const __half* srcA = g_Ah + (size_t)(m0 + sr) * N_NODES + (t & 7) * 8
                         + (size_t)ck0 * BKC;
    const __half* srcB = g_Bt + (size_t)sr * N_NODES + (t & 7) * 8
                         + (size_t)ck0 * BKC;
    const uint32_t dstA = SWZ(sr * 128 + sc);
    const uint32_t dstB = SWZ(sr * 128 + sc);

    const int lr16 = lane & 15;
    const int lhalf = (lane >> 4) * 16;
    uint32_t aBase[2], bBase[2];
    #pragma unroll
    for (int mt = 0; mt < 2; mt++)
        aBase[mt] = (wm * 32 + mt * 16 + lr16) * 128 + lhalf;
    #pragma unroll
    for (int bt = 0; bt < 2; bt++)
        bBase[bt] = (wn * 32 + bt * 16 + lr16) * 128 + lhalf;

    float acc[2][4][4];
    #pragma unroll
    for (int mt = 0; mt < 2; mt++)
        #pragma unroll
        for (int nt = 0; nt < 4; nt++)
            #pragma unroll
            for (int r = 0; r < 4; r++) acc[mt][nt][r] = 0.0f;

    // prologue: chunks 0..2 of this split
    #pragma unroll
    for (int c = 0; c < STAGES - 1; c++) {
        const uint32_t sA = smBase + c * STAGE_B;
        const uint32_t sB = sA + A_TILE_B;
        const int ko = c * BKC;
        cp16(sA + dstA,        srcA + ko);
        cp16(sA + dstA + 4096, srcA + ko + 32ull * N_NODES);
        #pragma unroll
        for (int rb = 0; rb < 4; rb++)
            cp16(sB + dstB + rb * 4096, srcB + ko + (size_t)rb * 32 * N_NODES);
        asm volatile("cp.async.commit_group;" ::: "memory");
    }

    const uint32_t* dishp = reinterpret_cast<const uint32_t*>(g_dish);

    for (int c = 0; c < CPS; c++) {
        const int ck = ck0 + c;
        asm volatile("cp.async.wait_group %0;" :: "n"(STAGES - 2) : "memory");
        __syncthreads();

        // wait for dis group ck (usually already set), then load dis2 regs
        while (*(volatile int*)&g_done[ck] < 64) __nanosleep(128);
        __threadfence();
        uint32_t d2[8];
        const uint32_t* dp = dishp + ck * 32 + (lane & 3);
        #pragma unroll
        for (int j = 0; j < 8; j++) d2[j] = dp[j * 4];

        const uint32_t sA = smBase + (c & (STAGES - 1)) * STAGE_B;
        const uint32_t sB = sA + A_TILE_B;

        #pragma unroll
        for (int kk = 0; kk < BKC / 16; kk++) {
            uint32_t aF[2][4], bF[2][4];
            #pragma unroll
            for (int mt = 0; mt < 2; mt++)
                ldsm4(aF[mt], sA + SWZ(aBase[mt] + kk * 32));
            #pragma unroll
            for (int bt = 0; bt < 2; bt++) {
                ldsm4(bF[bt], sB + SWZ(bBase[bt] + kk * 32));
                bF[bt][0] = hmul2u(bF[bt][0], d2[2 * kk]);      // k 0-7 half
                bF[bt][1] = hmul2u(bF[bt][1], d2[2 * kk]);
                bF[bt][2] = hmul2u(bF[bt][2], d2[2 * kk + 1]);  // k 8-15 half
                bF[bt][3] = hmul2u(bF[bt][3], d2[2 * kk + 1]);
            }
            #pragma unroll
            for (int mt = 0; mt < 2; mt++)
                #pragma unroll
                for (int nt = 0; nt < 4; nt++)
                    hmma(acc[mt][nt], aF[mt],
                         bF[nt >> 1][nt & 1], bF[nt >> 1][(nt & 1) + 2]);
        }

        const int cn = c + STAGES - 1;
        if (cn < CPS) {
            const uint32_t nA = smBase + (cn & (STAGES - 1)) * STAGE_B;
            const uint32_t nB = nA + A_TILE_B;
            const int ko = cn * BKC;
            cp16(nA + dstA,        srcA + ko);
            cp16(nA + dstA + 4096, srcA + ko + 32ull * N_NODES);
            #pragma unroll
            for (int rb = 0; rb < 4; rb++)
                cp16(nB + dstB + rb * 4096, srcB + ko + (size_t)rb * 32 * N_NODES);
        }
        asm volatile("cp.async.commit_group;" ::: "memory");
    }

    // epilogue: raw partial (dis[i] + leaky applied in reduce)
    float* pout = g_part + (size_t)s * (N_NODES * D_OUT);
    const int gid = lane >> 2;
    const int cid = (lane & 3) * 2;
    #pragma unroll
    for (int mt = 0; mt < 2; mt++) {
        const int r0 = m0 + wm * 32 + mt * 16 + gid;
        #pragma unroll
        for (int nt = 0; nt < 4; nt++) {
            const int col = wn * 32 + nt * 8 + cid;
            *reinterpret_cast<float2*>(pout + (size_t)r0 * D_OUT + col)
                = make_float2(acc[mt][nt][0], acc[mt][nt][1]);
            *reinterpret_cast<float2*>(pout + (size_t)(r0 + 8) * D_OUT + col)
                = make_float2(acc[mt][nt][2], acc[mt][nt][3]);
        }
    }
}

// ---------------------------------------------------------------------------
// Reduce: out = leaky(dis[i] * sum_s part_s); also resets flags for replay.
// ---------------------------------------------------------------------------
__global__ void __launch_bounds__(256) k_reduce(float* __restrict__ out)
{
    const int i4 = blockIdx.x * 256 + threadIdx.x;      // 0..262143
    const float4* p = reinterpret_cast<const float4*>(g_part);
    const int S4 = N_NODES * D_OUT / 4;                 // 262144
    float4 v0 = p[i4];
    float4 v1 = p[i4 + S4];
    float4 v2 = p[i4 + 2 * S4];
    float4 v3 = p[i4 + 3 * S4];
    const float d = g_dis[i4 >> 5];
    float4 r;
    r.x = d * (v0.x + v1.x + v2.x + v3.x);
    r.y = d * (v0.y + v1.y + v2.y + v3.y);
    r.z = d * (v0.z + v1.z + v2.z + v3.z);
    r.w = d * (v0.w + v1.w + v2.w + v3.w);
    r.x = (r.x >= 0.0f) ? r.x : NEG_SLOPE * r.x;
    r.y = (r.y >= 0.0f) ? r.y : NEG_SLOPE * r.y;
    r.z = (r.z >= 0.0f) ? r.z : NEG_SLOPE * r.z;
    r.w = (r.w >= 0.0f) ? r.w : NEG_SLOPE * r.w;
    reinterpret_cast<float4*>(out)[i4] = r;

    if (blockIdx.x == 0 && threadIdx.x < N_NODES / 64)
        g_done[threadIdx.x] = 0;                        // reset for next replay
}

// ---------------------------------------------------------------------------
extern "C" void kernel_launch(void* const* d_in, const int* in_sizes, int n_in,
                              void* d_out, int out_size)
{
    const float* H = (const float*)d_in[0];   // [8192, 200]
    const float* A = (const float*)d_in[1];   // [8192, 8192]
    const float* W = (const float*)d_in[2];   // [200, 128]
    const float* b = (const float*)d_in[3];   // [128]

    float* out  = (float*)d_out;                     // [8192, 128]
    float* Aout = out + (size_t)N_NODES * D_OUT;     // [8192, 8192] exact fp32 A'

    k_hw<<<N_NODES / K2_ROWS, 256>>>(H, W, b);       // B (unscaled) — no K1 dep

    cudaFuncSetAttribute(k_fused, cudaFuncAttributeMaxDynamicSharedMemorySize,
                         STAGES * STAGE_B);
    k_fused<<<GRID_FUSED, 256, STAGES * STAGE_B>>>(A, Aout);

    k_reduce<<<N_NODES * D_OUT / 4 / 256, 256>>>(out);
}

// round 16
// speedup vs baseline: 1.7559x; 1.7559x over previous
#include <cuda_runtime.h>
#include <cuda_fp16.h>
#include <cstdint>

// Shapes (fixed)
#define N_NODES 8192
#define D_IN    200
#define D_OUT   128
#define NEG_SLOPE 0.01f

// K3 tiling (R4-proven: BM=64, 128 CTAs, 256 thr)
#define BM      64
#define BKC     64              // K per pipeline chunk (64 fp16 = 128B rows)
#define NCHUNKS (N_NODES / BKC) // 128
#define STAGES  4
#define A_TILE_B  (BM * BKC * 2)        // 8 KB
#define B_TILE_B  (D_OUT * BKC * 2)     // 16 KB
#define STAGE_B   (A_TILE_B + B_TILE_B) // 24 KB
#define SWZ(off) ((off) ^ (((off) >> 3) & 0x70))

// Scratch (__device__ globals: allocation-free rule)
__device__ float  g_dis[N_NODES];                       // d^{-1/2}
__device__ __half g_Ah[(size_t)N_NODES * N_NODES];      // fp16 sigmoid-clamp(A)
__device__ __half g_Bt[(size_t)D_OUT * N_NODES];        // [n][k] fp16 dis[k]*(HW+b)

// ---------------------------------------------------------------------------
// Kernel 1 (R4-proven, ~97us = DRAM floor for 640MB): A' = max(sigmoid,0.1)
// -> fp32 out + fp16 mirror; rowsum -> rsqrt.
// ---------------------------------------------------------------------------
__global__ void __launch_bounds__(256) k_sigmoid_rowsum(
    const float* __restrict__ A, float* __restrict__ Aout)
{
    const int row = blockIdx.x;
    const float4* ap = reinterpret_cast<const float4*>(A + (size_t)row * N_NODES);
    float4* op = reinterpret_cast<float4*>(Aout + (size_t)row * N_NODES);
    uint2* hp = reinterpret_cast<uint2*>(g_Ah + (size_t)row * N_NODES);

    float sum = 0.0f;
    #pragma unroll 2
    for (int i = threadIdx.x; i < N_NODES / 4; i += 256) {
        float4 v = ap[i];
        float4 s;
        s.x = fmaxf(__fdividef(1.0f, 1.0f + __expf(-v.x)), 0.1f);
        s.y = fmaxf(__fdividef(1.0f, 1.0f + __expf(-v.y)), 0.1f);
        s.z = fmaxf(__fdividef(1.0f, 1.0f + __expf(-v.z)), 0.1f);
        s.w = fmaxf(__fdividef(1.0f, 1.0f + __expf(-v.w)), 0.1f);
        op[i] = s;
        __half2 p0 = __floats2half2_rn(s.x, s.y);
        __half2 p1 = __floats2half2_rn(s.z, s.w);
        uint2 u;
        u.x = *reinterpret_cast<uint32_t*>(&p0);
        u.y = *reinterpret_cast<uint32_t*>(&p1);
        hp[i] = u;
        sum += (s.x + s.y) + (s.z + s.w);
    }

    #pragma unroll
    for (int off = 16; off > 0; off >>= 1)
        sum += __shfl_xor_sync(0xFFFFFFFFu, sum, off);

    __shared__ float ws[8];
    const int wid = threadIdx.x >> 5;
    const int lane = threadIdx.x & 31;
    if (lane == 0) ws[wid] = sum;
    __syncthreads();
    if (threadIdx.x == 0) {
        float tot = 0.0f;
        #pragma unroll
        for (int w = 0; w < 8; w++) tot += ws[w];
        g_dis[row] = rsqrtf(tot);
    }
}

// ---------------------------------------------------------------------------
// Kernel 2 (REWRITTEN — was 51us latency-bound): g_Bt[j][k] =
// fp16( dis[k] * (H[k,:]@W[:,j] + b[j]) ), transposed.
// Block = 16 k-rows x 128 j, 128 threads; thread = 4k x 4j (16 FMA chains,
// 16 FMA per float4 W load). H staged in smem (warp-broadcast). Grid 512.
// ---------------------------------------------------------------------------
#define K2_ROWS 16
__global__ void __launch_bounds__(128) k_hw(
    const float* __restrict__ H, const float* __restrict__ W,
    const float* __restrict__ b)
{
    __shared__ float hs[K2_ROWS][D_IN];     // 12.8 KB
    const int kb = blockIdx.x * K2_ROWS;
    const int tid = threadIdx.x;

    // stage H tile: 16 rows x 50 float4
    for (int idx = tid; idx < K2_ROWS * (D_IN / 4); idx += 128) {
        const int r = idx / (D_IN / 4), c = idx % (D_IN / 4);
        reinterpret_cast<float4*>(&hs[r][0])[c] =
            reinterpret_cast<const float4*>(H + (size_t)(kb + r) * D_IN)[c];
    }
    __syncthreads();

    const int tx = tid & 31;          // j group (same for whole warp? no: lanes)
    const int ty = tid >> 5;          // 0..3 -> 4-row slab
    const int j0 = tx * 4;
    const int k0 = ty * 4;            // local row base (0,4,8,12)

    const float4 bj = *reinterpret_cast<const float4*>(b + j0);
    float4 a0 = bj, a1 = bj, a2 = bj, a3 = bj;
    const float* h0p = hs[k0];
    const float* h1p = hs[k0 + 1];
    const float* h2p = hs[k0 + 2];
    const float* h3p = hs[k0 + 3];

    #pragma unroll 4
    for (int i = 0; i < D_IN; i++) {
        const float4 w4 = *reinterpret_cast<const float4*>(W + i * D_OUT + j0);
        const float h0 = h0p[i];
        const float h1 = h1p[i];
        const float h2 = h2p[i];
        const float h3 = h3p[i];
        a0.x = fmaf(h0, w4.x, a0.x); a0.y = fmaf(h0, w4.y, a0.y);
        a0.z = fmaf(h0, w4.z, a0.z); a0.w = fmaf(h0, w4.w, a0.w);
        a1.x = fmaf(h1, w4.x, a1.x); a1.y = fmaf(h1, w4.y, a1.y);
        a1.z = fmaf(h1, w4.z, a1.z); a1.w = fmaf(h1, w4.w, a1.w);
        a2.x = fmaf(h2, w4.x, a2.x); a2.y = fmaf(h2, w4.y, a2.y);
        a2.z = fmaf(h2, w4.z, a2.z); a2.w = fmaf(h2, w4.w, a2.w);
        a3.x = fmaf(h3, w4.x, a3.x); a3.y = fmaf(h3, w4.y, a3.y);
        a3.z = fmaf(h3, w4.z, a3.z); a3.w = fmaf(h3, w4.w, a3.w);
    }

    const int kg = kb + k0;
    const float d0 = g_dis[kg];
    const float d1 = g_dis[kg + 1];
    const float d2 = g_dis[kg + 2];
    const float d3 = g_dis[kg + 3];

    // transposed stores: per j, k-pairs (kg,kg+1) and (kg+2,kg+3); kg%4==0
    __half2 p;
    __half* base0 = &g_Bt[(size_t)(j0 + 0) * N_NODES + kg];
    __half* base1 = &g_Bt[(size_t)(j0 + 1) * N_NODES + kg];
    __half* base2 = &g_Bt[(size_t)(j0 + 2) * N_NODES + kg];
    __half* base3 = &g_Bt[(size_t)(j0 + 3) * N_NODES + kg];
    p = __floats2half2_rn(a0.x * d0, a1.x * d1); *reinterpret_cast<__half2*>(base0)     = p;
    p = __floats2half2_rn(a2.x * d2, a3.x * d3); *reinterpret_cast<__half2*>(base0 + 2) = p;
    p = __floats2half2_rn(a0.y * d0, a1.y * d1); *reinterpret_cast<__half2*>(base1)     = p;
    p = __floats2half2_rn(a2.y * d2, a3.y * d3); *reinterpret_cast<__half2*>(base1 + 2) = p;
    p = __floats2half2_rn(a0.z * d0, a1.z * d1); *reinterpret_cast<__half2*>(base2)     = p;
    p = __floats2half2_rn(a2.z * d2, a3.z * d3); *reinterpret_cast<__half2*>(base2 + 2) = p;
    p = __floats2half2_rn(a0.w * d0, a1.w * d1); *reinterpret_cast<__half2*>(base3)     = p;
    p = __floats2half2_rn(a2.w * d2, a3.w * d3); *reinterpret_cast<__half2*>(base3 + 2) = p;
}

// ---------------------------------------------------------------------------
// K3 (R4-proven, byte-identical): fp16 HMMA GEMM. 128 CTAs (M=64), 256 thr,
// cp.async 4-stage, ldmatrix, mma.m16n8k16.f32.
// ---------------------------------------------------------------------------
__device__ __forceinline__ uint32_t s2u(const void* p) {
    uint32_t a;
    asm("{ .reg .u64 t; cvta.to.shared.u64 t, %1; cvt.u32.u64 %0, t; }"
        : "=r"(a) : "l"(p));
    return a;
}
__device__ __forceinline__ void cp16(uint32_t dst, const void* src) {
    asm volatile("cp.async.cg.shared.global [%0], [%1], 16;"
                 :: "r"(dst), "l"(src) : "memory");
}
__device__ __forceinline__ void ldsm4(uint32_t* r, uint32_t addr) {
    asm volatile("ldmatrix.sync.aligned.m8n8.x4.shared.b16 {%0,%1,%2,%3}, [%4];"
                 : "=r"(r[0]), "=r"(r[1]), "=r"(r[2]), "=r"(r[3]) : "r"(addr));
}
__device__ __forceinline__ void hmma(float* d, const uint32_t* a,
                                     uint32_t b0, uint32_t b1) {
    asm volatile(
        "mma.sync.aligned.m16n8k16.row.col.f32.f16.f16.f32 "
        "{%0,%1,%2,%3},{%4,%5,%6,%7},{%8,%9},{%0,%1,%2,%3};"
        : "+f"(d[0]), "+f"(d[1]), "+f"(d[2]), "+f"(d[3])
        : "r"(a[0]), "r"(a[1]), "r"(a[2]), "r"(a[3]), "r"(b0), "r"(b1));
}

__global__ void __launch_bounds__(256, 1) k_gemm_h(float* __restrict__ out)
{
    extern __shared__ __align__(1024) char dsm[];   // STAGES * 24KB = 96KB
    const int t   = threadIdx.x;
    const int wid = t >> 5, lane = t & 31;
    const int wm  = wid & 1;          // m slab (0..1) * 32
    const int wn  = wid >> 1;         // n slab (0..3) * 32
    const int m0  = blockIdx.x * BM;
    const uint32_t smBase = s2u(dsm);

    // ---- staging maps: 16B chunks, 128B rows, XOR swizzle
    const int sr  = t >> 3;           // 0..31
    const int sc  = (t & 7) * 16;     // byte col in 128B row
    const __half* srcA = g_Ah + (size_t)(m0 + sr) * N_NODES + (t & 7) * 8;
    const __half* srcB = g_Bt + (size_t)sr * N_NODES + (t & 7) * 8;
    const uint32_t dstA = SWZ(sr * 128 + sc);           // + 4096 for rows+32
    const uint32_t dstB = SWZ(sr * 128 + sc);           // + 4096 per 32 rows

    // ---- ldmatrix address components
    const int lr16 = lane & 15;
    const int lhalf = (lane >> 4) * 16;
    uint32_t aBase[2], bBase[2];
    #pragma unroll
    for (int mt = 0; mt < 2; mt++)
        aBase[mt] = (wm * 32 + mt * 16 + lr16) * 128 + lhalf;
    #pragma unroll
    for (int bt = 0; bt < 2; bt++)
        bBase[bt] = (wn * 32 + bt * 16 + lr16) * 128 + lhalf;

    float acc[2][4][4];
    #pragma unroll
    for (int mt = 0; mt < 2; mt++)
        #pragma unroll
        for (int nt = 0; nt < 4; nt++)
            #pragma unroll
            for (int r = 0; r < 4; r++) acc[mt][nt][r] = 0.0f;

    // ---- prologue: issue STAGES-1 chunks
    #pragma unroll
    for (int c = 0; c < STAGES - 1; c++) {
        const uint32_t sA = smBase + c * STAGE_B;
        const uint32_t sB = sA + A_TILE_B;
        const int ko = c * BKC;
        cp16(sA + dstA,        srcA + ko);
        cp16(sA + dstA + 4096, srcA + ko + 32ull * N_NODES);
        #pragma unroll
        for (int rb = 0; rb < 4; rb++)
            cp16(sB + dstB + rb * 4096, srcB + ko + (size_t)rb * 32 * N_NODES);
        asm volatile("cp.async.commit_group;" ::: "memory");
    }

    for (int c = 0; c < NCHUNKS; c++) {
        asm volatile("cp.async.wait_group %0;" :: "n"(STAGES - 2) : "memory");
        __syncthreads();

        const uint32_t sA = smBase + (c & (STAGES - 1)) * STAGE_B;
        const uint32_t sB = sA + A_TILE_B;

        #pragma unroll
        for (int kk = 0; kk < BKC / 16; kk++) {
            uint32_t aF[2][4], bF[2][4];
            #pragma unroll
            for (int mt = 0; mt < 2; mt++)
                ldsm4(aF[mt], sA + SWZ(aBase[mt] + kk * 32));
            #pragma unroll
            for (int bt = 0; bt < 2; bt++)
                ldsm4(bF[bt], sB + SWZ(bBase[bt] + kk * 32));
            #pragma unroll
            for (int mt = 0; mt < 2; mt++)
                #pragma unroll
                for (int nt = 0; nt < 4; nt++)
                    hmma(acc[mt][nt], aF[mt],
                         bF[nt >> 1][nt & 1], bF[nt >> 1][(nt & 1) + 2]);
        }

        // issue chunk c + STAGES-1
        const int cn = c + STAGES - 1;
        if (cn < NCHUNKS) {
            const uint32_t nA = smBase + (cn & (STAGES - 1)) * STAGE_B;
            const uint32_t nB = nA + A_TILE_B;
            const int ko = cn * BKC;
            cp16(nA + dstA,        srcA + ko);
            cp16(nA + dstA + 4096, srcA + ko + 32ull * N_NODES);
            #pragma unroll
            for (int rb = 0; rb < 4; rb++)
                cp16(nB + dstB + rb * 4096, srcB + ko + (size_t)rb * 32 * N_NODES);
        }
        asm volatile("cp.async.commit_group;" ::: "memory");
    }

    // ---- epilogue: scale by dis[i], LeakyReLU, store
    const int gid = lane >> 2;
    const int cid = (lane & 3) * 2;
    #pragma unroll
    for (int mt = 0; mt < 2; mt++) {
        const int r0 = m0 + wm * 32 + mt * 16 + gid;
        const float d0 = g_dis[r0];
        const float d1 = g_dis[r0 + 8];
        #pragma unroll
        for (int nt = 0; nt < 4; nt++) {
            const int col = wn * 32 + nt * 8 + cid;
            float v0 = d0 * acc[mt][nt][0];
            float v1 = d0 * acc[mt][nt][1];
            float v2 = d1 * acc[mt][nt][2];
            float v3 = d1 * acc[mt][nt][3];
            v0 = (v0 >= 0.0f) ? v0 : NEG_SLOPE * v0;
            v1 = (v1 >= 0.0f) ? v1 : NEG_SLOPE * v1;
            v2 = (v2 >= 0.0f) ? v2 : NEG_SLOPE * v2;
            v3 = (v3 >= 0.0f) ? v3 : NEG_SLOPE * v3;
            *reinterpret_cast<float2*>(out + (size_t)r0 * D_OUT + col)
                = make_float2(v0, v1);
            *reinterpret_cast<float2*>(out + (size_t)(r0 + 8) * D_OUT + col)
                = make_float2(v2, v3);
        }
    }
}

// ---------------------------------------------------------------------------
extern "C" void kernel_launch(void* const* d_in, const int* in_sizes, int n_in,
                              void* d_out, int out_size)
{
    const float* H = (const float*)d_in[0];   // [8192, 200]
    const float* A = (const float*)d_in[1];   // [8192, 8192]
    const float* W = (const float*)d_in[2];   // [200, 128]
    const float* b = (const float*)d_in[3];   // [128]

    float* out  = (float*)d_out;                     // [8192, 128]
    float* Aout = out + (size_t)N_NODES * D_OUT;     // [8192, 8192] exact A'

    k_sigmoid_rowsum<<<N_NODES, 256>>>(A, Aout);
    k_hw<<<N_NODES / K2_ROWS, 128>>>(H, W, b);

    cudaFuncSetAttribute(k_gemm_h, cudaFuncAttributeMaxDynamicSharedMemorySize,
                         STAGES * STAGE_B);
    k_gemm_h<<<N_NODES / BM, 256, STAGES * STAGE_B>>>(out);
}